// round 16
// baseline (speedup 1.0000x reference)
#include <cuda_runtime.h>
#include <cuda_fp16.h>
#include <cstdint>

#define BB 8
#define TT 16
#define NN 1024
#define HH 128
#define NHEADS 8
#define SNP 4
#define NT 4096
#define EMAX 65536
#define LRELU_SLOPE 0.2f
#define DEL (4*NT*NHEADS)     // el/er offset between batch b and b+4 (within buffer)
#define DFE (4*NT*HH)         // feat offset between batch b and b+4 (within buffer)
#define DXH (4*TT*NN*HH)      // x (half) offset between batch b and b+4
#define GEMM_SMEM 49152       // 4 stages x (Ah 4K + Al 4K + B 4K)
#define BUF ((size_t)BB*NT)

// ---------------- scratch (device globals) ------------------------------------
__device__ __half g_xh[BB*TT*NN*HH];          // x, fp16 hi (plain row-major)
__device__ __half g_xl[BB*TT*NN*HH];          // x, fp16 lo
__device__ float g_feat5[5*BB*NT*HH];         // layer-0 feat, one buffer per iter
__device__ float g_el5[5*BB*NT*NHEADS];
__device__ float g_er5[5*BB*NT*NHEADS];
__device__ float g_feat1[BB*NT*HH];           // layer-1 feat (compact, per-iter reuse)
__device__ float g_el1[BB*NT*NHEADS];
__device__ float g_er1[BB*NT*NHEADS];
__device__ __half g_h0h[BB*NT*HH];            // layer0 out fp16 hi
__device__ __half g_h0l[BB*NT*HH];
__device__ float g_last[BB*NN*HH];            // RAW pooled (pre-norm)
__device__ __half g_lh[BB*NN*HH];             // raw pooled fp16 hi
__device__ __half g_ll[BB*NN*HH];
__device__ float g_stats[2][16];              // ping-pong per-batch sum,sumsq
__device__ float g_wsum[2][HH];
__device__ int   g_deg[NT];                   // zeroed by k_out tail
__device__ int   g_off[NT+1];
__device__ int   g_eid[EMAX];
__device__ int   g_srcs[EMAX];
__device__ __half g_wth[2][HH*HH];            // W^T fp16 (plain [n][k])

// ---------------- helpers ------------------------------------------------------
__device__ __forceinline__ unsigned packh(float x, float y) {
    __half2 t = __floats2half2_rn(x, y);
    return *(unsigned*)&t;
}
__device__ __forceinline__ float2 h2f2(unsigned u) {
    __half2 t = *(__half2*)&u;
    return make_float2(__half2float(t.x), __half2float(t.y));
}
__device__ __forceinline__ void mma16816(float* c, unsigned a0, unsigned a1,
                                         unsigned a2, unsigned a3,
                                         unsigned b0, unsigned b1) {
    asm volatile(
        "mma.sync.aligned.m16n8k16.row.col.f32.f16.f16.f32 "
        "{%0,%1,%2,%3},{%4,%5,%6,%7},{%8,%9},{%0,%1,%2,%3};\n"
        : "+f"(c[0]), "+f"(c[1]), "+f"(c[2]), "+f"(c[3])
        : "r"(a0), "r"(a1), "r"(a2), "r"(a3), "r"(b0), "r"(b1));
}
__device__ __forceinline__ void ldsm4(unsigned& r0, unsigned& r1,
                                      unsigned& r2, unsigned& r3, unsigned addr) {
    asm volatile("ldmatrix.sync.aligned.m8n8.x4.shared.b16 {%0,%1,%2,%3}, [%4];"
        : "=r"(r0), "=r"(r1), "=r"(r2), "=r"(r3) : "r"(addr));
}
__device__ __forceinline__ void cpasync16(unsigned saddr, const void* gptr) {
    asm volatile("cp.async.ca.shared.global [%0], [%1], 16;"
        :: "r"(saddr), "l"(gptr));
}
template<int N> __device__ __forceinline__ void cp_wait() {
    asm volatile("cp.async.wait_group %0;\n" :: "n"(N));
}

// ---------------- prolog: x + wconv + CSR-count + wsum ------------------------
__global__ __launch_bounds__(256) void k_prolog(
        const float* __restrict__ in, const float* __restrict__ Win,
        const float* __restrict__ bin, const float* __restrict__ spat,
        const float* __restrict__ temp, const float* __restrict__ W0,
        const float* __restrict__ W1, const int* __restrict__ edst, int E) {
    int blk = blockIdx.x;
    if (blk < 32768) {
        int idx = blk*256 + threadIdx.x;
        int h = (idx & 63) * 2;
        int n = (idx >> 6) & 1023;
        int t = (idx >> 16) & 15;
        int b = idx >> 20;
        size_t ib = ((size_t)(b*TT + t)*NN + n)*2;
        float i0 = in[ib], i1 = in[ib+1];
        float tv = temp[n*16+t];
        float v0 = i0*Win[h]   + i1*Win[128+h]   + bin[h]   + spat[n*128+h]   + tv;
        float v1 = i0*Win[h+1] + i1*Win[128+h+1] + bin[h+1] + spat[n*128+h+1] + tv;
        size_t row = ((size_t)(b*TT + t)*NN + n)*HH;
        __half h0 = __float2half_rn(v0);
        __half h1 = __float2half_rn(v1);
        *(unsigned*)&g_xh[row + h] = packh(v0, v1);
        *(unsigned*)&g_xl[row + h] = packh(v0 - __half2float(h0),
                                           v1 - __half2float(h1));
    } else if (blk < 32896) {
        int id = (blk - 32768)*256 + threadIdx.x;
        int layer = id >> 14;
        int r = id & 16383;
        int k = r >> 7, n = r & 127;
        float w = (layer ? W1 : W0)[k*HH + n];
        g_wth[layer][n*HH + k] = __float2half_rn(w);
    } else if (blk < 33052) {
        int i = (blk - 32896)*256 + threadIdx.x;
        if (i < E) atomicAdd(&g_deg[edst[i]], 1);
    } else {
        int id = threadIdx.x;
        int layer = id >> 7, n = id & 127;
        const float* W = layer ? W1 : W0;
        float s = 0.f;
        for (int k = 0; k < HH; k++) s += W[k*HH + n];
        g_wsum[layer][n] = s;
    }
}

// ---------------- CSR build part 1: scan + fill --------------------------------
__global__ __launch_bounds__(1024) void k_csr1(const int* __restrict__ edst, int E) {
    __shared__ int sh[1024];
    __shared__ int scnt[NT];
    int tid = threadIdx.x;
    int d0 = g_deg[tid*4+0], d1 = g_deg[tid*4+1], d2 = g_deg[tid*4+2], d3 = g_deg[tid*4+3];
    scnt[tid*4+0] = 0; scnt[tid*4+1] = 0; scnt[tid*4+2] = 0; scnt[tid*4+3] = 0;
    int tot = d0+d1+d2+d3;
    sh[tid] = tot; __syncthreads();
    for (int o = 1; o < 1024; o <<= 1) {
        int v = (tid >= o) ? sh[tid-o] : 0;
        __syncthreads();
        sh[tid] += v;
        __syncthreads();
    }
    int excl = sh[tid] - tot;
    g_off[tid*4+0] = excl;
    g_off[tid*4+1] = excl + d0;
    g_off[tid*4+2] = excl + d0 + d1;
    g_off[tid*4+3] = excl + d0 + d1 + d2;
    if (tid == 1023) g_off[NT] = sh[1023];
    __syncthreads();
    for (int i = tid; i < E; i += 1024) {
        int v = edst[i];
        int slot = g_off[v] + atomicAdd(&scnt[v], 1);
        g_eid[slot] = i;
    }
}

// ---------------- CSR build part 2: sort + gather ------------------------------
__global__ __launch_bounds__(1024) void k_csr2(const int* __restrict__ esrc) {
    int v = blockIdx.x*1024 + threadIdx.x;
    if (v >= NT) return;
    int o0 = g_off[v];
    int d = g_deg[v]; if (d > 10) d = 10;
    for (int i = 1; i < d; i++) {
        int key = g_eid[o0+i];
        int j = i-1;
        while (j >= 0 && g_eid[o0+j] > key) { g_eid[o0+j+1] = g_eid[o0+j]; j--; }
        g_eid[o0+j+1] = key;
    }
    for (int j = 0; j < d; j++) g_srcs[o0+j] = esrc[g_eid[o0+j]];
}

// ---------------- MMA GEMM: 4-stage cp.async ring, LDSM, fused el/er -----------
// mode 0: fresh x rows  -> g_feat5[it] slots s0..3     (grid B*(4-s0)*8)
// mode 1: pooled rows   -> g_feat5[it] slot 0 (+LN)    (grid B*8)
// mode 2: layer 1 (A=h0)-> g_feat1                     (grid B*NT/128)
__global__ __launch_bounds__(256, 2) void k_gemm(int mode, int it, int left,
                                                 const float* __restrict__ al,
                                                 const float* __restrict__ ar) {
    extern __shared__ __half dyn[];
    __shared__ float s_al[128], s_ar[128], s_w[128];
    int tid = threadIdx.x;
    int lane = tid & 31, warp = tid >> 5;
    int rrow = tid & 127;
    int k8 = tid >> 7;

    if (tid < 128) { s_al[tid] = al[tid]; s_ar[tid] = ar[tid]; s_w[tid] = g_wsum[0][tid]; }

    size_t abase, fbase;
    const __half *asrc_h, *asrc_l;
    float *featp, *elp, *erp;
    int layer;
    if (mode == 0) {
        int s0 = (it > 0) ? 1 : 0;
        int ns = 4 - s0;
        int b = blockIdx.x / (ns*8);
        int rem = blockIdx.x - b*(ns*8);
        int s = s0 + rem/8;
        int n0 = (rem & 7)*128;
        int t = left + s - s0;
        abase = (size_t)((b*TT + t)*NN + n0);
        asrc_h = g_xh; asrc_l = g_xl;
        fbase = (size_t)(b*NT + s*NN + n0);
        layer = 0;
    } else if (mode == 1) {
        int b = blockIdx.x >> 3;
        int n0 = (blockIdx.x & 7)*128;
        abase = (size_t)(b*NN + n0);
        asrc_h = g_lh; asrc_l = g_ll;
        fbase = (size_t)(b*NT + n0);
        layer = 0;
    } else {
        abase = (size_t)blockIdx.x * 128;
        asrc_h = g_h0h; asrc_l = g_h0l;
        fbase = abase;
        layer = 1;
    }
    if (mode == 2) { featp = g_feat1; elp = g_el1; erp = g_er1; }
    else {
        featp = g_feat5 + (size_t)it*BUF*HH;
        elp   = g_el5   + (size_t)it*BUF*NHEADS;
        erp   = g_er5   + (size_t)it*BUF*NHEADS;
    }

    const __half* ah_src = asrc_h + (abase + rrow)*HH + k8*8;
    const __half* al_src = asrc_l + (abase + rrow)*HH + k8*8;
    const __half* bh_src = &g_wth[layer][rrow*HH + k8*8];
    unsigned st_off2 = (unsigned)((((rrow>>3)*2 + k8)*64 + (rrow&7)*8) * 2);
    unsigned smem_base = (unsigned)__cvta_generic_to_shared(dyn);

    int mm = lane >> 3;
    unsigned a_off = (unsigned)(((warp*2 + (mm&1))*2 + (mm>>1))*128 + (lane&7)*16);
    unsigned b_off = (unsigned)((((mm>>1)*2) + (mm&1))*128 + (lane&7)*16);

    float acc[16][4];
    #pragma unroll
    for (int nt = 0; nt < 16; nt++)
        #pragma unroll
        for (int j = 0; j < 4; j++) acc[nt][j] = 0.f;

    #pragma unroll
    for (int s = 0; s < 3; s++) {
        unsigned sb = smem_base + s*12288;
        cpasync16(sb + st_off2,        ah_src + s*16);
        cpasync16(sb + 4096 + st_off2, al_src + s*16);
        cpasync16(sb + 8192 + st_off2, bh_src + s*16);
        asm volatile("cp.async.commit_group;\n");
    }

    #pragma unroll
    for (int kc = 0; kc < 8; kc++) {
        if (kc < 6) cp_wait<2>();
        else if (kc == 6) cp_wait<1>();
        else cp_wait<0>();
        __syncthreads();
        if (kc + 3 < 8) {
            int s = kc + 3;
            unsigned sb = smem_base + (s&3)*12288;
            cpasync16(sb + st_off2,        ah_src + s*16);
            cpasync16(sb + 4096 + st_off2, al_src + s*16);
            cpasync16(sb + 8192 + st_off2, bh_src + s*16);
            asm volatile("cp.async.commit_group;\n");
        }
        unsigned stage = smem_base + (kc&3)*12288;
        unsigned ah0, ah1, ah2, ah3, al0, al1, al2, al3;
        ldsm4(ah0, ah1, ah2, ah3, stage + a_off);
        ldsm4(al0, al1, al2, al3, stage + 4096 + a_off);
        unsigned bbase = stage + 8192 + b_off;
        #pragma unroll
        for (int j = 0; j < 8; j++) {
            unsigned b0, b1, b2, b3;
            ldsm4(b0, b1, b2, b3, bbase + j*512);
            mma16816(acc[2*j],   ah0, ah1, ah2, ah3, b0, b1);
            mma16816(acc[2*j],   al0, al1, al2, al3, b0, b1);
            mma16816(acc[2*j+1], ah0, ah1, ah2, ah3, b2, b3);
            mma16816(acc[2*j+1], al0, al1, al2, al3, b2, b3);
        }
    }

    // layernorm affine correction (pooled rows only; uniform per block)
    float cs = 1.f, csh = 0.f;
    if (mode == 1) {
        int b = blockIdx.x >> 3;
        const float inv = 1.0f/(float)(NN*HH);
        float s1 = g_stats[(it-1)&1][b*2];
        float s2 = g_stats[(it-1)&1][b*2+1];
        float mu = s1*inv;
        float var = s2*inv - mu*mu;
        float rstd = rsqrtf(var + 1e-5f);
        cs = rstd; csh = -mu*rstd;
    }

    // epilogue: correct, store feat, fused el/er
    size_t r0 = fbase + warp*16 + (lane >> 2);
    size_t r8 = r0 + 8;
    float pl0[8], pl8[8], pr0[8], pr8[8];
    #pragma unroll
    for (int h = 0; h < 8; h++) { pl0[h]=0.f; pl8[h]=0.f; pr0[h]=0.f; pr8[h]=0.f; }
    #pragma unroll
    for (int nt = 0; nt < 16; nt++) {
        int c = nt*8 + (lane & 3)*2;
        int h = nt >> 1;
        acc[nt][0] = acc[nt][0]*cs + csh*s_w[c];
        acc[nt][1] = acc[nt][1]*cs + csh*s_w[c+1];
        acc[nt][2] = acc[nt][2]*cs + csh*s_w[c];
        acc[nt][3] = acc[nt][3]*cs + csh*s_w[c+1];
        float a0 = s_al[c], a1 = s_al[c+1];
        float b0 = s_ar[c], b1 = s_ar[c+1];
        pl0[h] += acc[nt][0]*a0 + acc[nt][1]*a1;
        pr0[h] += acc[nt][0]*b0 + acc[nt][1]*b1;
        pl8[h] += acc[nt][2]*a0 + acc[nt][3]*a1;
        pr8[h] += acc[nt][2]*b0 + acc[nt][3]*b1;
        *(float2*)&featp[r0*HH + c] = make_float2(acc[nt][0], acc[nt][1]);
        *(float2*)&featp[r8*HH + c] = make_float2(acc[nt][2], acc[nt][3]);
    }
    #pragma unroll
    for (int h = 0; h < 8; h++) {
        pl0[h] += __shfl_xor_sync(0xffffffffu, pl0[h], 1);
        pl0[h] += __shfl_xor_sync(0xffffffffu, pl0[h], 2);
        pl8[h] += __shfl_xor_sync(0xffffffffu, pl8[h], 1);
        pl8[h] += __shfl_xor_sync(0xffffffffu, pl8[h], 2);
        pr0[h] += __shfl_xor_sync(0xffffffffu, pr0[h], 1);
        pr0[h] += __shfl_xor_sync(0xffffffffu, pr0[h], 2);
        pr8[h] += __shfl_xor_sync(0xffffffffu, pr8[h], 1);
        pr8[h] += __shfl_xor_sync(0xffffffffu, pr8[h], 2);
    }
    if ((lane & 3) == 0) {
        #pragma unroll
        for (int h = 0; h < 8; h++) {
            elp[r0*8 + h] = pl0[h];
            elp[r8*8 + h] = pl8[h];
            erp[r0*8 + h] = pr0[h];
            erp[r8*8 + h] = pr8[h];
        }
    }
}

// ---------------- GAT gather: batch-paired (b, b+4), distributed softmax -------
__device__ __forceinline__ void gat_gather2(int v, int bNT, int lane,
                                            const float* __restrict__ featp,
                                            const float* __restrict__ elp,
                                            const float* __restrict__ erp,
                                            float4& O0, float4& O1) {
    int o0 = g_off[v];
    int d = g_deg[v];
    int head = lane >> 2;
    int h8 = lane & 7;

    int vb = (bNT + v)*8 + h8;
    float erv0 = erp[vb];
    float erv1 = erp[vb + DEL];
    float ee0[3], ee1[3];
    #pragma unroll
    for (int s = 0; s < 3; s++) {
        int j = s*4 + (lane >> 3);
        int sj = g_srcs[o0 + j];
        int eb = (bNT + sj)*8 + h8;
        float t0 = elp[eb] + erv0;
        float t1 = elp[eb + DEL] + erv1;
        t0 = t0 > 0.f ? t0 : LRELU_SLOPE*t0;
        t1 = t1 > 0.f ? t1 : LRELU_SLOPE*t1;
        float w0 = __expf(t0), w1 = __expf(t1);
        ee0[s] = (j < d) ? w0 : 0.f;
        ee1[s] = (j < d) ? w1 : 0.f;
    }

    int sreg[10];
    #pragma unroll
    for (int j = 0; j < 10; j++) sreg[j] = g_srcs[o0 + j];

    float a0[10], a1[10];
    float ss0 = 0.f, ss1 = 0.f;
    #pragma unroll
    for (int j = 0; j < 10; j++) {
        int src = ((j&3)<<3) + head;
        a0[j] = __shfl_sync(0xffffffffu, ee0[j>>2], src);
        a1[j] = __shfl_sync(0xffffffffu, ee1[j>>2], src);
        ss0 += a0[j]; ss1 += a1[j];
    }
    float r0 = 1.0f/ss0, r1 = 1.0f/ss1;

    float4 A0 = make_float4(0.f,0.f,0.f,0.f);
    float4 A1 = make_float4(0.f,0.f,0.f,0.f);
    int co = lane*4;
    #pragma unroll
    for (int j = 0; j < 10; j++) {
        const float* fp = &featp[(size_t)(bNT + sreg[j])*HH + co];
        float4 f0 = *(const float4*)fp;
        float4 f1 = *(const float4*)(fp + DFE);
        A0.x += a0[j]*f0.x; A0.y += a0[j]*f0.y; A0.z += a0[j]*f0.z; A0.w += a0[j]*f0.w;
        A1.x += a1[j]*f1.x; A1.y += a1[j]*f1.y; A1.z += a1[j]*f1.z; A1.w += a1[j]*f1.w;
    }
    A0.x *= r0; A0.y *= r0; A0.z *= r0; A0.w *= r0;
    A1.x *= r1; A1.y *= r1; A1.z *= r1; A1.w *= r1;
    O0 = A0; O1 = A1;
}

__device__ __forceinline__ float elu1(float x) {
    return x > 0.f ? x : __expf(x) - 1.f;
}

// ---------------- layer-0 aggregation (batch-paired; zeroes stats[it&1]) -------
__global__ __launch_bounds__(256) void k_agg0(const float* __restrict__ bias, int it) {
    if (blockIdx.x == 0 && threadIdx.x < 16)
        ((float*)g_stats)[(it&1)*16 + threadIdx.x] = 0.f;
    int warp = (blockIdx.x * blockDim.x + threadIdx.x) >> 5;
    int lane = threadIdx.x & 31;
    int v = warp & (NT-1);
    int b0 = warp >> 12;
    const float* featp = g_feat5 + (size_t)it*BUF*HH;
    const float* elp   = g_el5   + (size_t)it*BUF*NHEADS;
    const float* erp   = g_er5   + (size_t)it*BUF*NHEADS;
    float4 A0, A1;
    gat_gather2(v, b0*NT, lane, featp, elp, erp, A0, A1);
    float4 bv = *(const float4*)&bias[lane*4];
    A0.x = elu1(A0.x + bv.x); A0.y = elu1(A0.y + bv.y);
    A0.z = elu1(A0.z + bv.z); A0.w = elu1(A0.w + bv.w);
    A1.x = elu1(A1.x + bv.x); A1.y = elu1(A1.y + bv.y);
    A1.z = elu1(A1.z + bv.z); A1.w = elu1(A1.w + bv.w);
    int c = lane*4;
    size_t rb0 = ((size_t)(b0*NT + v))*HH;
    size_t rb1 = rb0 + (size_t)DFE;
    __half q0 = __float2half_rn(A0.x), q1 = __float2half_rn(A0.y);
    __half q2 = __float2half_rn(A0.z), q3 = __float2half_rn(A0.w);
    uint2 hv0 = {packh(A0.x, A0.y), packh(A0.z, A0.w)};
    uint2 lv0 = {packh(A0.x - __half2float(q0), A0.y - __half2float(q1)),
                 packh(A0.z - __half2float(q2), A0.w - __half2float(q3))};
    *(uint2*)&g_h0h[rb0 + c] = hv0;
    *(uint2*)&g_h0l[rb0 + c] = lv0;
    __half u0 = __float2half_rn(A1.x), u1 = __float2half_rn(A1.y);
    __half u2 = __float2half_rn(A1.z), u3 = __float2half_rn(A1.w);
    uint2 hv1 = {packh(A1.x, A1.y), packh(A1.z, A1.w)};
    uint2 lv1 = {packh(A1.x - __half2float(u0), A1.y - __half2float(u1)),
                 packh(A1.z - __half2float(u2), A1.w - __half2float(u3))};
    *(uint2*)&g_h0h[rb1 + c] = hv1;
    *(uint2*)&g_h0l[rb1 + c] = lv1;
}

// ---------------- fused layer-1 agg + residual + pooling (batch-paired) --------
__global__ __launch_bounds__(256) void k_agg1pool(const float* __restrict__ bias,
                                                  const float* __restrict__ q,
                                                  int iter, int left) {
    __shared__ float ssc[8][2];
    __shared__ float sbuf[8][2][128];
    __shared__ float sst[8][4];
    int tid = threadIdx.x, lane = tid & 31, w = tid >> 5;
    int b0 = blockIdx.x >> 9;
    int n0 = (blockIdx.x & 511) * 2;
    int node = n0 + (w >> 2);
    int s = w & 3;
    int v = s*NN + node;

    float4 A0, A1;
    gat_gather2(v, b0*NT, lane, g_feat1, g_el1, g_er1, A0, A1);
    float4 bv = *(const float4*)&bias[lane*4];
    A0.x += bv.x; A0.y += bv.y; A0.z += bv.z; A0.w += bv.w;
    A1.x += bv.x; A1.y += bv.y; A1.z += bv.z; A1.w += bv.w;

    int c = lane*4;
    if (iter > 0 && s == 0) {
        const float inv = 1.0f/(float)(NN*HH);
        #pragma unroll
        for (int bp = 0; bp < 2; bp++) {
            int bb = b0 + 4*bp;
            float s1 = g_stats[(iter-1)&1][bb*2];
            float s2 = g_stats[(iter-1)&1][bb*2+1];
            float mu = s1*inv;
            float var = s2*inv - mu*mu;
            float rstd = rsqrtf(var + 1e-5f);
            float4 lv = *(const float4*)&g_last[((size_t)(bb*NN + node))*HH + c];
            float4& A = bp ? A1 : A0;
            A.x += (lv.x-mu)*rstd; A.y += (lv.y-mu)*rstd;
            A.z += (lv.z-mu)*rstd; A.w += (lv.w-mu)*rstd;
        }
    } else {
        int t = left + s - (iter > 0 ? 1 : 0);
        size_t xrow = ((size_t)((b0*TT + t)*NN + node))*HH + c;
        {
            uint2 ah = *(const uint2*)&g_xh[xrow];
            uint2 al = *(const uint2*)&g_xl[xrow];
            float2 a0 = h2f2(ah.x), a1 = h2f2(ah.y);
            float2 l0 = h2f2(al.x), l1 = h2f2(al.y);
            A0.x += a0.x+l0.x; A0.y += a0.y+l0.y; A0.z += a1.x+l1.x; A0.w += a1.y+l1.y;
        }
        {
            uint2 ah = *(const uint2*)&g_xh[xrow + (size_t)DXH];
            uint2 al = *(const uint2*)&g_xl[xrow + (size_t)DXH];
            float2 a0 = h2f2(ah.x), a1 = h2f2(ah.y);
            float2 l0 = h2f2(al.x), l1 = h2f2(al.y);
            A1.x += a0.x+l0.x; A1.y += a0.y+l0.y; A1.z += a1.x+l1.x; A1.w += a1.y+l1.y;
        }
    }

    float4 qv = *(const float4*)&q[node*HH + c];
    float sc0 = A0.x*qv.x + A0.y*qv.y + A0.z*qv.z + A0.w*qv.w;
    float sc1 = A1.x*qv.x + A1.y*qv.y + A1.z*qv.z + A1.w*qv.w;
    #pragma unroll
    for (int o = 16; o > 0; o >>= 1) {
        sc0 += __shfl_xor_sync(0xffffffffu, sc0, o);
        sc1 += __shfl_xor_sync(0xffffffffu, sc1, o);
    }
    if (lane == 0) { ssc[w][0] = sc0; ssc[w][1] = sc1; }
    __syncthreads();

    int basew = (w >> 2) * 4;
    #pragma unroll
    for (int bp = 0; bp < 2; bp++) {
        float c0 = ssc[basew][bp], c1 = ssc[basew+1][bp];
        float c2 = ssc[basew+2][bp], c3 = ssc[basew+3][bp];
        float m = fmaxf(fmaxf(c0, c1), fmaxf(c2, c3));
        float e0 = __expf(c0-m), e1 = __expf(c1-m), e2 = __expf(c2-m), e3 = __expf(c3-m);
        float alpha = __expf(ssc[basew+s][bp]-m) / (e0+e1+e2+e3);
        const float4& A = bp ? A1 : A0;
        *(float4*)&sbuf[w][bp][c] = make_float4(A.x*alpha, A.y*alpha, A.z*alpha, A.w*alpha);
    }
    __syncthreads();

    int ns = tid >> 7, cc = tid & 127;
    int wb = ns*4;
    #pragma unroll
    for (int bp = 0; bp < 2; bp++) {
        float lastv = sbuf[wb][bp][cc] + sbuf[wb+1][bp][cc]
                    + sbuf[wb+2][bp][cc] + sbuf[wb+3][bp][cc];
        int bb = b0 + 4*bp;
        size_t lr = ((size_t)(bb*NN + n0 + ns))*HH;
        g_last[lr + cc] = lastv;
        __half hi = __float2half_rn(lastv);
        g_lh[lr + cc] = hi;
        g_ll[lr + cc] = __float2half_rn(lastv - __half2float(hi));
        float s1v = lastv, s2v = lastv*lastv;
        #pragma unroll
        for (int o = 16; o > 0; o >>= 1) {
            s1v += __shfl_xor_sync(0xffffffffu, s1v, o);
            s2v += __shfl_xor_sync(0xffffffffu, s2v, o);
        }
        if (lane == 0) { sst[w][bp*2] = s1v; sst[w][bp*2+1] = s2v; }
    }
    __syncthreads();
    if (tid < 4) {
        int bp = tid >> 1, which = tid & 1;
        float acc = 0.f;
        #pragma unroll
        for (int ww = 0; ww < 8; ww++) acc += sst[ww][bp*2 + which];
        atomicAdd(&g_stats[iter&1][(b0 + 4*bp)*2 + which], acc);
    }
}

// ---------------- output head (+ zero deg for next call) -----------------------
__global__ void k_out(const float* __restrict__ w1, const float* __restrict__ b1,
                      const float* __restrict__ w2, const float* __restrict__ b2,
                      float* __restrict__ out) {
    int bn = blockIdx.x;
    int tid = threadIdx.x;
    if (bn < 32) { g_deg[bn*128 + tid] = 0; }
    int b = bn >> 10;
    int n = bn & 1023;
    int lane = tid & 31, w = tid >> 5;
    __shared__ float sred[4][12];
    const float inv = 1.0f/(float)(NN*HH);
    float s1 = g_stats[0][b*2];
    float s2 = g_stats[0][b*2+1];
    float mu = s1*inv;
    float var = s2*inv - mu*mu;
    float rstd = rsqrtf(var + 1e-5f);
    float lv = (g_last[(size_t)bn*128 + tid] - mu)*rstd;
    float w2v = w2[tid];
    float p[12];
    #pragma unroll
    for (int s = 0; s < 12; s++) {
        float t = lv*w1[s] + b1[s];
        t = t > 0.f ? t : 0.f;
        p[s] = t*w2v;
    }
    #pragma unroll
    for (int s = 0; s < 12; s++) {
        #pragma unroll
        for (int o = 16; o > 0; o >>= 1) p[s] += __shfl_xor_sync(0xffffffffu, p[s], o);
    }
    if (lane == 0) {
        #pragma unroll
        for (int s = 0; s < 12; s++) sred[w][s] = p[s];
    }
    __syncthreads();
    if (tid < 12)
        out[((size_t)b*12 + tid)*NN + n] = sred[0][tid]+sred[1][tid]+sred[2][tid]+sred[3][tid] + b2[0];
}

// =============================================================================
extern "C" void kernel_launch(void* const* d_in, const int* in_sizes, int n_in,
                              void* d_out, int out_size) {
    const float* inputs   = (const float*)d_in[0];
    const float* W_in     = (const float*)d_in[1];
    const float* b_in     = (const float*)d_in[2];
    const float* spat     = (const float*)d_in[3];
    const float* temp     = (const float*)d_in[4];
    const float* gat_w0   = (const float*)d_in[5];
    const float* gat_al0  = (const float*)d_in[6];
    const float* gat_ar0  = (const float*)d_in[7];
    const float* gat_b0   = (const float*)d_in[8];
    const float* gat_w1   = (const float*)d_in[9];
    const float* gat_al1  = (const float*)d_in[10];
    const float* gat_ar1  = (const float*)d_in[11];
    const float* gat_b1   = (const float*)d_in[12];
    const float* agg_q    = (const float*)d_in[13];
    const float* w_out1   = (const float*)d_in[14];
    const float* b_out1   = (const float*)d_in[15];
    const float* w_out2   = (const float*)d_in[16];
    const float* b_out2   = (const float*)d_in[17];
    const int*   esrc     = (const int*)d_in[18];
    const int*   edst     = (const int*)d_in[19];
    int E = in_sizes[18];

    cudaFuncSetAttribute(k_gemm, cudaFuncAttributeMaxDynamicSharedMemorySize,
                         GEMM_SMEM);

    const int lefts[5] = {0, 4, 7, 10, 13};

    // side stream + events for overlapping the iteration-independent fresh-x
    // GEMMs with the serial chain (fork-join pattern; valid under graph capture)
    cudaStream_t s1;
    cudaStreamCreateWithFlags(&s1, cudaStreamNonBlocking);
    cudaEvent_t evP, evF[5];
    cudaEventCreateWithFlags(&evP, cudaEventDisableTiming);
    for (int i = 0; i < 5; i++)
        cudaEventCreateWithFlags(&evF[i], cudaEventDisableTiming);

    k_prolog<<<33053, 256>>>(inputs, W_in, b_in, spat, temp,
                             gat_w0, gat_w1, edst, E);
    cudaEventRecord(evP, 0);

    // fresh-x layer-0 GEMMs on side stream (depend only on prolog)
    cudaStreamWaitEvent(s1, evP, 0);
    for (int it = 0; it < 5; it++) {
        int ns = (it > 0) ? 3 : 4;
        k_gemm<<<BB*ns*8, 256, GEMM_SMEM, s1>>>(0, it, lefts[it], gat_al0, gat_ar0);
        cudaEventRecord(evF[it], s1);
    }

    // main chain on stream 0
    k_csr1<<<1, 1024>>>(edst, E);
    k_csr2<<<4, 1024>>>(esrc);

    for (int it = 0; it < 5; it++) {
        if (it > 0)
            k_gemm<<<BB*8, 256, GEMM_SMEM>>>(1, it, lefts[it], gat_al0, gat_ar0);
        cudaStreamWaitEvent(0, evF[it], 0);
        k_agg0<<<2048, 256>>>(gat_b0, it);
        k_gemm<<<(BB*NT)/128, 256, GEMM_SMEM>>>(2, it, lefts[it], gat_al1, gat_ar1);
        k_agg1pool<<<2048, 256>>>(gat_b1, agg_q, it, lefts[it]);
    }

    k_out<<<BB*NN, 128>>>(w_out1, b_out1, w_out2, b_out2, (float*)d_out);
}

// round 17
// speedup vs baseline: 1.0414x; 1.0414x over previous
#include <cuda_runtime.h>
#include <cuda_fp16.h>
#include <cstdint>

#define BB 8
#define TT 16
#define NN 1024
#define HH 128
#define NHEADS 8
#define SNP 4
#define NT 4096
#define EMAX 65536
#define LRELU_SLOPE 0.2f
#define DEL (4*NT*NHEADS)     // el/er offset between batch b and b+4
#define DFE (4*NT*HH)         // feat offset between batch b and b+4
#define DXH (4*TT*NN*HH)      // x (half) offset between batch b and b+4
#define GEMM_SMEM 49152       // 4 stages x (Ah 4K + Al 4K + B 4K)

// ---------------- scratch (device globals) ------------------------------------
__device__ __half g_xh[BB*TT*NN*HH];          // x, fp16 hi (plain row-major)
__device__ __half g_xl[BB*TT*NN*HH];          // x, fp16 lo
__device__ float g_feat[BB*NT*HH];
__device__ float g_el[BB*NT*NHEADS];
__device__ float g_er[BB*NT*NHEADS];
__device__ __half g_h0h[BB*NT*HH];            // layer0 out fp16 hi
__device__ __half g_h0l[BB*NT*HH];
__device__ float g_last[BB*NN*HH];            // RAW pooled (pre-norm)
__device__ __half g_lh[BB*NN*HH];             // raw pooled fp16 hi
__device__ __half g_ll[BB*NN*HH];
__device__ float g_stats[2][16];              // ping-pong per-batch sum,sumsq
__device__ float g_wsum[2][HH];
__device__ int   g_deg[NT];                   // zeroed by k_out tail
__device__ int   g_off[NT+1];
__device__ int   g_eid[EMAX];
__device__ int   g_srcs[EMAX];
__device__ __half g_wth[2][HH*HH];            // W^T fp16 (plain [n][k])

// ---------------- helpers ------------------------------------------------------
__device__ __forceinline__ unsigned packh(float x, float y) {
    __half2 t = __floats2half2_rn(x, y);
    return *(unsigned*)&t;
}
__device__ __forceinline__ float2 h2f2(unsigned u) {
    __half2 t = *(__half2*)&u;
    return make_float2(__half2float(t.x), __half2float(t.y));
}
__device__ __forceinline__ void mma16816(float* c, unsigned a0, unsigned a1,
                                         unsigned a2, unsigned a3,
                                         unsigned b0, unsigned b1) {
    asm volatile(
        "mma.sync.aligned.m16n8k16.row.col.f32.f16.f16.f32 "
        "{%0,%1,%2,%3},{%4,%5,%6,%7},{%8,%9},{%0,%1,%2,%3};\n"
        : "+f"(c[0]), "+f"(c[1]), "+f"(c[2]), "+f"(c[3])
        : "r"(a0), "r"(a1), "r"(a2), "r"(a3), "r"(b0), "r"(b1));
}
__device__ __forceinline__ void ldsm4(unsigned& r0, unsigned& r1,
                                      unsigned& r2, unsigned& r3, unsigned addr) {
    asm volatile("ldmatrix.sync.aligned.m8n8.x4.shared.b16 {%0,%1,%2,%3}, [%4];"
        : "=r"(r0), "=r"(r1), "=r"(r2), "=r"(r3) : "r"(addr));
}
__device__ __forceinline__ void cpasync8(unsigned saddr, const void* gptr) {
    asm volatile("cp.async.ca.shared.global [%0], [%1], 8;"
        :: "r"(saddr), "l"(gptr));
}
template<int N> __device__ __forceinline__ void cp_wait() {
    asm volatile("cp.async.wait_group %0;\n" :: "n"(N));
}

// ---------------- prolog: x + wconv + CSR-count + wsum ------------------------
__global__ __launch_bounds__(256) void k_prolog(
        const float* __restrict__ in, const float* __restrict__ Win,
        const float* __restrict__ bin, const float* __restrict__ spat,
        const float* __restrict__ temp, const float* __restrict__ W0,
        const float* __restrict__ W1, const int* __restrict__ edst, int E) {
    int blk = blockIdx.x;
    if (blk < 32768) {
        int idx = blk*256 + threadIdx.x;
        int h = (idx & 63) * 2;
        int n = (idx >> 6) & 1023;
        int t = (idx >> 16) & 15;
        int b = idx >> 20;
        size_t ib = ((size_t)(b*TT + t)*NN + n)*2;
        float i0 = in[ib], i1 = in[ib+1];
        float tv = temp[n*16+t];
        float v0 = i0*Win[h]   + i1*Win[128+h]   + bin[h]   + spat[n*128+h]   + tv;
        float v1 = i0*Win[h+1] + i1*Win[128+h+1] + bin[h+1] + spat[n*128+h+1] + tv;
        size_t row = ((size_t)(b*TT + t)*NN + n)*HH;
        __half h0 = __float2half_rn(v0);
        __half h1 = __float2half_rn(v1);
        *(unsigned*)&g_xh[row + h] = packh(v0, v1);
        *(unsigned*)&g_xl[row + h] = packh(v0 - __half2float(h0),
                                           v1 - __half2float(h1));
    } else if (blk < 32896) {
        int id = (blk - 32768)*256 + threadIdx.x;
        int layer = id >> 14;
        int r = id & 16383;
        int k = r >> 7, n = r & 127;
        float w = (layer ? W1 : W0)[k*HH + n];
        g_wth[layer][n*HH + k] = __float2half_rn(w);
    } else if (blk < 33052) {
        int i = (blk - 32896)*256 + threadIdx.x;
        if (i < E) atomicAdd(&g_deg[edst[i]], 1);
    } else {
        int id = threadIdx.x;
        int layer = id >> 7, n = id & 127;
        const float* W = layer ? W1 : W0;
        float s = 0.f;
        for (int k = 0; k < HH; k++) s += W[k*HH + n];
        g_wsum[layer][n] = s;
    }
}

// ---------------- CSR build part 1: scan + fill --------------------------------
__global__ __launch_bounds__(1024) void k_csr1(const int* __restrict__ edst, int E) {
    __shared__ int sh[1024];
    __shared__ int scnt[NT];
    int tid = threadIdx.x;
    int d0 = g_deg[tid*4+0], d1 = g_deg[tid*4+1], d2 = g_deg[tid*4+2], d3 = g_deg[tid*4+3];
    scnt[tid*4+0] = 0; scnt[tid*4+1] = 0; scnt[tid*4+2] = 0; scnt[tid*4+3] = 0;
    int tot = d0+d1+d2+d3;
    sh[tid] = tot; __syncthreads();
    for (int o = 1; o < 1024; o <<= 1) {
        int v = (tid >= o) ? sh[tid-o] : 0;
        __syncthreads();
        sh[tid] += v;
        __syncthreads();
    }
    int excl = sh[tid] - tot;
    g_off[tid*4+0] = excl;
    g_off[tid*4+1] = excl + d0;
    g_off[tid*4+2] = excl + d0 + d1;
    g_off[tid*4+3] = excl + d0 + d1 + d2;
    if (tid == 1023) g_off[NT] = sh[1023];
    __syncthreads();
    for (int i = tid; i < E; i += 1024) {
        int v = edst[i];
        int slot = g_off[v] + atomicAdd(&scnt[v], 1);
        g_eid[slot] = i;
    }
}

// ---------------- CSR build part 2: sort + gather ------------------------------
__global__ __launch_bounds__(1024) void k_csr2(const int* __restrict__ esrc) {
    int v = blockIdx.x*1024 + threadIdx.x;
    if (v >= NT) return;
    int o0 = g_off[v];
    int d = g_deg[v]; if (d > 10) d = 10;
    for (int i = 1; i < d; i++) {
        int key = g_eid[o0+i];
        int j = i-1;
        while (j >= 0 && g_eid[o0+j] > key) { g_eid[o0+j+1] = g_eid[o0+j]; j--; }
        g_eid[o0+j+1] = key;
    }
    for (int j = 0; j < d; j++) g_srcs[o0+j] = esrc[g_eid[o0+j]];
}

// ---------------- MMA GEMM: 512 threads (16 warps, 16x64 warp tile) ------------
// 256 blocks; 4-stage cp.async ring; LDSM fragments; fused el/er.
// 32 acc regs/thread -> ~64 total -> 2 CTAs x 16 warps = 32 warps/SM.
__global__ __launch_bounds__(512, 2) void k_gemm(int layer, int iter, int left,
                                                 const float* __restrict__ al,
                                                 const float* __restrict__ ar) {
    extern __shared__ __half dyn[];
    __shared__ float s_al[128], s_ar[128], s_w[128];
    int tid = threadIdx.x;
    int lane = tid & 31, warp = tid >> 5;
    int wm = warp >> 1, wn = warp & 1;
    int block_row = blockIdx.x * 128;

    if (layer == 0 && blockIdx.x == 0 && tid < 16)
        ((float*)g_stats)[(iter&1)*16 + tid] = 0.f;
    if (tid < 128) { s_al[tid] = al[tid]; s_ar[tid] = ar[tid]; s_w[tid] = g_wsum[0][tid]; }

    // staging: thread handles row rrow = tid>>2, k-quarter q = tid&3 (8B each)
    int rrow = tid >> 2;
    int q = tid & 3;
    const __half *ah_src, *al_src;
    {
        int row_g = block_row + rrow;
        size_t off;
        if (layer == 0) {
            int b = row_g >> 12, s = (row_g >> 10) & 3, n = row_g & 1023;
            if (iter > 0 && s == 0) {
                off = ((size_t)(b*NN + n))*HH;
                ah_src = g_lh + off; al_src = g_ll + off;
            } else {
                int t = left + s - (iter > 0 ? 1 : 0);
                off = ((size_t)((b*TT + t)*NN + n))*HH;
                ah_src = g_xh + off; al_src = g_xl + off;
            }
        } else {
            off = ((size_t)row_g)*HH;
            ah_src = g_h0h + off; al_src = g_h0l + off;
        }
        ah_src += q*4; al_src += q*4;
    }
    const __half* bh_src = &g_wth[layer][rrow*HH + q*4];
    // tile-packed STS offset (bytes): tile = (row>>3)*2 + (q>>1), within (row&7)*8 + (q&1)*4 halves
    unsigned st_off2 = (unsigned)(((((rrow>>3)*2 + (q>>1))*64 + (rrow&7)*8 + (q&1)*4)) * 2);
    unsigned smem_base = (unsigned)__cvta_generic_to_shared(dyn);

    // ldmatrix lane addresses (bytes within 4KB chunk region)
    int mm = lane >> 3;
    unsigned a_off = (unsigned)(((wm*2 + (mm&1))*2 + (mm>>1))*128 + (lane&7)*16);
    unsigned b_off = (unsigned)(wn*2048 + (((mm>>1)*2) + (mm&1))*128 + (lane&7)*16);

    float acc[8][4];
    #pragma unroll
    for (int nt = 0; nt < 8; nt++)
        #pragma unroll
        for (int j = 0; j < 4; j++) acc[nt][j] = 0.f;

    // prologue: issue chunks 0..2 (one commit group each)
    #pragma unroll
    for (int s = 0; s < 3; s++) {
        unsigned sb = smem_base + s*12288;
        cpasync8(sb + st_off2,        ah_src + s*16);
        cpasync8(sb + 4096 + st_off2, al_src + s*16);
        cpasync8(sb + 8192 + st_off2, bh_src + s*16);
        asm volatile("cp.async.commit_group;\n");
    }

    #pragma unroll
    for (int kc = 0; kc < 8; kc++) {
        if (kc < 6) cp_wait<2>();
        else if (kc == 6) cp_wait<1>();
        else cp_wait<0>();
        __syncthreads();
        if (kc + 3 < 8) {
            int s = kc + 3;
            unsigned sb = smem_base + (s&3)*12288;
            cpasync8(sb + st_off2,        ah_src + s*16);
            cpasync8(sb + 4096 + st_off2, al_src + s*16);
            cpasync8(sb + 8192 + st_off2, bh_src + s*16);
            asm volatile("cp.async.commit_group;\n");
        }
        unsigned stage = smem_base + (kc&3)*12288;
        unsigned ah0, ah1, ah2, ah3, al0, al1, al2, al3;
        ldsm4(ah0, ah1, ah2, ah3, stage + a_off);
        ldsm4(al0, al1, al2, al3, stage + 4096 + a_off);
        unsigned bbase = stage + 8192 + b_off;
        #pragma unroll
        for (int j = 0; j < 4; j++) {
            unsigned b0, b1, b2, b3;
            ldsm4(b0, b1, b2, b3, bbase + j*512);
            mma16816(acc[2*j],   ah0, ah1, ah2, ah3, b0, b1);
            mma16816(acc[2*j],   al0, al1, al2, al3, b0, b1);
            mma16816(acc[2*j+1], ah0, ah1, ah2, ah3, b2, b3);
            mma16816(acc[2*j+1], al0, al1, al2, al3, b2, b3);
        }
    }

    // layernorm affine correction (uniform per block: 128 rows within one s)
    float cs = 1.f, csh = 0.f;
    if (layer == 0 && iter > 0 && ((block_row >> 10) & 3) == 0) {
        int b = block_row >> 12;
        const float inv = 1.0f/(float)(NN*HH);
        float s1 = g_stats[(iter-1)&1][b*2];
        float s2 = g_stats[(iter-1)&1][b*2+1];
        float mu = s1*inv;
        float var = s2*inv - mu*mu;
        float rstd = rsqrtf(var + 1e-5f);
        cs = rstd; csh = -mu*rstd;
    }

    // epilogue: correct, store feat, fused el/er (4 heads: wn*4..wn*4+3)
    int r0 = block_row + wm*16 + (lane >> 2);
    int r8 = r0 + 8;
    float pl0[4], pl8[4], pr0[4], pr8[4];
    #pragma unroll
    for (int h = 0; h < 4; h++) { pl0[h]=0.f; pl8[h]=0.f; pr0[h]=0.f; pr8[h]=0.f; }
    #pragma unroll
    for (int nt = 0; nt < 8; nt++) {
        int c = wn*64 + nt*8 + (lane & 3)*2;
        int h = nt >> 1;
        acc[nt][0] = acc[nt][0]*cs + csh*s_w[c];
        acc[nt][1] = acc[nt][1]*cs + csh*s_w[c+1];
        acc[nt][2] = acc[nt][2]*cs + csh*s_w[c];
        acc[nt][3] = acc[nt][3]*cs + csh*s_w[c+1];
        float a0 = s_al[c], a1 = s_al[c+1];
        float b0 = s_ar[c], b1 = s_ar[c+1];
        pl0[h] += acc[nt][0]*a0 + acc[nt][1]*a1;
        pr0[h] += acc[nt][0]*b0 + acc[nt][1]*b1;
        pl8[h] += acc[nt][2]*a0 + acc[nt][3]*a1;
        pr8[h] += acc[nt][2]*b0 + acc[nt][3]*b1;
        *(float2*)&g_feat[(size_t)r0*HH + c] = make_float2(acc[nt][0], acc[nt][1]);
        *(float2*)&g_feat[(size_t)r8*HH + c] = make_float2(acc[nt][2], acc[nt][3]);
    }
    #pragma unroll
    for (int h = 0; h < 4; h++) {
        pl0[h] += __shfl_xor_sync(0xffffffffu, pl0[h], 1);
        pl0[h] += __shfl_xor_sync(0xffffffffu, pl0[h], 2);
        pl8[h] += __shfl_xor_sync(0xffffffffu, pl8[h], 1);
        pl8[h] += __shfl_xor_sync(0xffffffffu, pl8[h], 2);
        pr0[h] += __shfl_xor_sync(0xffffffffu, pr0[h], 1);
        pr0[h] += __shfl_xor_sync(0xffffffffu, pr0[h], 2);
        pr8[h] += __shfl_xor_sync(0xffffffffu, pr8[h], 1);
        pr8[h] += __shfl_xor_sync(0xffffffffu, pr8[h], 2);
    }
    if ((lane & 3) == 0) {
        #pragma unroll
        for (int h = 0; h < 4; h++) {
            g_el[(size_t)r0*8 + wn*4 + h] = pl0[h];
            g_el[(size_t)r8*8 + wn*4 + h] = pl8[h];
            g_er[(size_t)r0*8 + wn*4 + h] = pr0[h];
            g_er[(size_t)r8*8 + wn*4 + h] = pr8[h];
        }
    }
}

// ---------------- GAT gather: batch-paired (b, b+4), distributed softmax -------
__device__ __forceinline__ void gat_gather2(int v, int bNT, int lane,
                                            float4& O0, float4& O1) {
    int o0 = g_off[v];
    int d = g_deg[v];
    int head = lane >> 2;
    int h8 = lane & 7;

    int vb = (bNT + v)*8 + h8;
    float erv0 = g_er[vb];
    float erv1 = g_er[vb + DEL];
    float ee0[3], ee1[3];
    #pragma unroll
    for (int s = 0; s < 3; s++) {
        int j = s*4 + (lane >> 3);
        int sj = g_srcs[o0 + j];
        int eb = (bNT + sj)*8 + h8;
        float t0 = g_el[eb] + erv0;
        float t1 = g_el[eb + DEL] + erv1;
        t0 = t0 > 0.f ? t0 : LRELU_SLOPE*t0;
        t1 = t1 > 0.f ? t1 : LRELU_SLOPE*t1;
        float w0 = __expf(t0), w1 = __expf(t1);
        ee0[s] = (j < d) ? w0 : 0.f;
        ee1[s] = (j < d) ? w1 : 0.f;
    }

    int sreg[10];
    #pragma unroll
    for (int j = 0; j < 10; j++) sreg[j] = g_srcs[o0 + j];

    float a0[10], a1[10];
    float ss0 = 0.f, ss1 = 0.f;
    #pragma unroll
    for (int j = 0; j < 10; j++) {
        int src = ((j&3)<<3) + head;
        a0[j] = __shfl_sync(0xffffffffu, ee0[j>>2], src);
        a1[j] = __shfl_sync(0xffffffffu, ee1[j>>2], src);
        ss0 += a0[j]; ss1 += a1[j];
    }
    float r0 = 1.0f/ss0, r1 = 1.0f/ss1;

    float4 A0 = make_float4(0.f,0.f,0.f,0.f);
    float4 A1 = make_float4(0.f,0.f,0.f,0.f);
    int co = lane*4;
    #pragma unroll
    for (int j = 0; j < 10; j++) {
        const float* fp = &g_feat[(size_t)(bNT + sreg[j])*HH + co];
        float4 f0 = *(const float4*)fp;
        float4 f1 = *(const float4*)(fp + DFE);
        A0.x += a0[j]*f0.x; A0.y += a0[j]*f0.y; A0.z += a0[j]*f0.z; A0.w += a0[j]*f0.w;
        A1.x += a1[j]*f1.x; A1.y += a1[j]*f1.y; A1.z += a1[j]*f1.z; A1.w += a1[j]*f1.w;
    }
    A0.x *= r0; A0.y *= r0; A0.z *= r0; A0.w *= r0;
    A1.x *= r1; A1.y *= r1; A1.z *= r1; A1.w *= r1;
    O0 = A0; O1 = A1;
}

__device__ __forceinline__ float elu1(float x) {
    return x > 0.f ? x : __expf(x) - 1.f;
}

// ---------------- layer-0 aggregation (batch-paired) ---------------------------
__global__ __launch_bounds__(256) void k_agg0(const float* __restrict__ bias) {
    int warp = (blockIdx.x * blockDim.x + threadIdx.x) >> 5;
    int lane = threadIdx.x & 31;
    int v = warp & (NT-1);
    int b0 = warp >> 12;
    float4 A0, A1;
    gat_gather2(v, b0*NT, lane, A0, A1);
    float4 bv = *(const float4*)&bias[lane*4];
    A0.x = elu1(A0.x + bv.x); A0.y = elu1(A0.y + bv.y);
    A0.z = elu1(A0.z + bv.z); A0.w = elu1(A0.w + bv.w);
    A1.x = elu1(A1.x + bv.x); A1.y = elu1(A1.y + bv.y);
    A1.z = elu1(A1.z + bv.z); A1.w = elu1(A1.w + bv.w);
    int c = lane*4;
    size_t rb0 = ((size_t)(b0*NT + v))*HH;
    size_t rb1 = rb0 + (size_t)DFE;
    __half q0 = __float2half_rn(A0.x), q1 = __float2half_rn(A0.y);
    __half q2 = __float2half_rn(A0.z), q3 = __float2half_rn(A0.w);
    uint2 hv0 = {packh(A0.x, A0.y), packh(A0.z, A0.w)};
    uint2 lv0 = {packh(A0.x - __half2float(q0), A0.y - __half2float(q1)),
                 packh(A0.z - __half2float(q2), A0.w - __half2float(q3))};
    *(uint2*)&g_h0h[rb0 + c] = hv0;
    *(uint2*)&g_h0l[rb0 + c] = lv0;
    __half u0 = __float2half_rn(A1.x), u1 = __float2half_rn(A1.y);
    __half u2 = __float2half_rn(A1.z), u3 = __float2half_rn(A1.w);
    uint2 hv1 = {packh(A1.x, A1.y), packh(A1.z, A1.w)};
    uint2 lv1 = {packh(A1.x - __half2float(u0), A1.y - __half2float(u1)),
                 packh(A1.z - __half2float(u2), A1.w - __half2float(u3))};
    *(uint2*)&g_h0h[rb1 + c] = hv1;
    *(uint2*)&g_h0l[rb1 + c] = lv1;
}

// ---------------- fused layer-1 agg + residual + pooling (batch-paired) --------
__global__ __launch_bounds__(256) void k_agg1pool(const float* __restrict__ bias,
                                                  const float* __restrict__ q,
                                                  int iter, int left) {
    __shared__ float ssc[8][2];
    __shared__ float sbuf[8][2][128];
    __shared__ float sst[8][4];
    int tid = threadIdx.x, lane = tid & 31, w = tid >> 5;
    int b0 = blockIdx.x >> 9;
    int n0 = (blockIdx.x & 511) * 2;
    int node = n0 + (w >> 2);
    int s = w & 3;
    int v = s*NN + node;

    float4 A0, A1;
    gat_gather2(v, b0*NT, lane, A0, A1);
    float4 bv = *(const float4*)&bias[lane*4];
    A0.x += bv.x; A0.y += bv.y; A0.z += bv.z; A0.w += bv.w;
    A1.x += bv.x; A1.y += bv.y; A1.z += bv.z; A1.w += bv.w;

    int c = lane*4;
    if (iter > 0 && s == 0) {
        const float inv = 1.0f/(float)(NN*HH);
        #pragma unroll
        for (int bp = 0; bp < 2; bp++) {
            int bb = b0 + 4*bp;
            float s1 = g_stats[(iter-1)&1][bb*2];
            float s2 = g_stats[(iter-1)&1][bb*2+1];
            float mu = s1*inv;
            float var = s2*inv - mu*mu;
            float rstd = rsqrtf(var + 1e-5f);
            float4 lv = *(const float4*)&g_last[((size_t)(bb*NN + node))*HH + c];
            float4& A = bp ? A1 : A0;
            A.x += (lv.x-mu)*rstd; A.y += (lv.y-mu)*rstd;
            A.z += (lv.z-mu)*rstd; A.w += (lv.w-mu)*rstd;
        }
    } else {
        int t = left + s - (iter > 0 ? 1 : 0);
        size_t xrow = ((size_t)((b0*TT + t)*NN + node))*HH + c;
        {
            uint2 ah = *(const uint2*)&g_xh[xrow];
            uint2 al = *(const uint2*)&g_xl[xrow];
            float2 a0 = h2f2(ah.x), a1 = h2f2(ah.y);
            float2 l0 = h2f2(al.x), l1 = h2f2(al.y);
            A0.x += a0.x+l0.x; A0.y += a0.y+l0.y; A0.z += a1.x+l1.x; A0.w += a1.y+l1.y;
        }
        {
            uint2 ah = *(const uint2*)&g_xh[xrow + (size_t)DXH];
            uint2 al = *(const uint2*)&g_xl[xrow + (size_t)DXH];
            float2 a0 = h2f2(ah.x), a1 = h2f2(ah.y);
            float2 l0 = h2f2(al.x), l1 = h2f2(al.y);
            A1.x += a0.x+l0.x; A1.y += a0.y+l0.y; A1.z += a1.x+l1.x; A1.w += a1.y+l1.y;
        }
    }

    float4 qv = *(const float4*)&q[node*HH + c];
    float sc0 = A0.x*qv.x + A0.y*qv.y + A0.z*qv.z + A0.w*qv.w;
    float sc1 = A1.x*qv.x + A1.y*qv.y + A1.z*qv.z + A1.w*qv.w;
    #pragma unroll
    for (int o = 16; o > 0; o >>= 1) {
        sc0 += __shfl_xor_sync(0xffffffffu, sc0, o);
        sc1 += __shfl_xor_sync(0xffffffffu, sc1, o);
    }
    if (lane == 0) { ssc[w][0] = sc0; ssc[w][1] = sc1; }
    __syncthreads();

    int basew = (w >> 2) * 4;
    #pragma unroll
    for (int bp = 0; bp < 2; bp++) {
        float c0 = ssc[basew][bp], c1 = ssc[basew+1][bp];
        float c2 = ssc[basew+2][bp], c3 = ssc[basew+3][bp];
        float m = fmaxf(fmaxf(c0, c1), fmaxf(c2, c3));
        float e0 = __expf(c0-m), e1 = __expf(c1-m), e2 = __expf(c2-m), e3 = __expf(c3-m);
        float alpha = __expf(ssc[basew+s][bp]-m) / (e0+e1+e2+e3);
        const float4& A = bp ? A1 : A0;
        *(float4*)&sbuf[w][bp][c] = make_float4(A.x*alpha, A.y*alpha, A.z*alpha, A.w*alpha);
    }
    __syncthreads();

    int ns = tid >> 7, cc = tid & 127;
    int wb = ns*4;
    #pragma unroll
    for (int bp = 0; bp < 2; bp++) {
        float lastv = sbuf[wb][bp][cc] + sbuf[wb+1][bp][cc]
                    + sbuf[wb+2][bp][cc] + sbuf[wb+3][bp][cc];
        int bb = b0 + 4*bp;
        size_t lr = ((size_t)(bb*NN + n0 + ns))*HH;
        g_last[lr + cc] = lastv;
        __half hi = __float2half_rn(lastv);
        g_lh[lr + cc] = hi;
        g_ll[lr + cc] = __float2half_rn(lastv - __half2float(hi));
        float s1v = lastv, s2v = lastv*lastv;
        #pragma unroll
        for (int o = 16; o > 0; o >>= 1) {
            s1v += __shfl_xor_sync(0xffffffffu, s1v, o);
            s2v += __shfl_xor_sync(0xffffffffu, s2v, o);
        }
        if (lane == 0) { sst[w][bp*2] = s1v; sst[w][bp*2+1] = s2v; }
    }
    __syncthreads();
    if (tid < 4) {
        int bp = tid >> 1, which = tid & 1;
        float acc = 0.f;
        #pragma unroll
        for (int ww = 0; ww < 8; ww++) acc += sst[ww][bp*2 + which];
        atomicAdd(&g_stats[iter&1][(b0 + 4*bp)*2 + which], acc);
    }
}

// ---------------- output head (+ zero deg for next call) -----------------------
__global__ void k_out(const float* __restrict__ w1, const float* __restrict__ b1,
                      const float* __restrict__ w2, const float* __restrict__ b2,
                      float* __restrict__ out) {
    int bn = blockIdx.x;
    int tid = threadIdx.x;
    if (bn < 32) { g_deg[bn*128 + tid] = 0; }
    int b = bn >> 10;
    int n = bn & 1023;
    int lane = tid & 31, w = tid >> 5;
    __shared__ float sred[4][12];
    const float inv = 1.0f/(float)(NN*HH);
    float s1 = g_stats[0][b*2];
    float s2 = g_stats[0][b*2+1];
    float mu = s1*inv;
    float var = s2*inv - mu*mu;
    float rstd = rsqrtf(var + 1e-5f);
    float lv = (g_last[(size_t)bn*128 + tid] - mu)*rstd;
    float w2v = w2[tid];
    float p[12];
    #pragma unroll
    for (int s = 0; s < 12; s++) {
        float t = lv*w1[s] + b1[s];
        t = t > 0.f ? t : 0.f;
        p[s] = t*w2v;
    }
    #pragma unroll
    for (int s = 0; s < 12; s++) {
        #pragma unroll
        for (int o = 16; o > 0; o >>= 1) p[s] += __shfl_xor_sync(0xffffffffu, p[s], o);
    }
    if (lane == 0) {
        #pragma unroll
        for (int s = 0; s < 12; s++) sred[w][s] = p[s];
    }
    __syncthreads();
    if (tid < 12)
        out[((size_t)b*12 + tid)*NN + n] = sred[0][tid]+sred[1][tid]+sred[2][tid]+sred[3][tid] + b2[0];
}

// =============================================================================
extern "C" void kernel_launch(void* const* d_in, const int* in_sizes, int n_in,
                              void* d_out, int out_size) {
    const float* inputs   = (const float*)d_in[0];
    const float* W_in     = (const float*)d_in[1];
    const float* b_in     = (const float*)d_in[2];
    const float* spat     = (const float*)d_in[3];
    const float* temp     = (const float*)d_in[4];
    const float* gat_w0   = (const float*)d_in[5];
    const float* gat_al0  = (const float*)d_in[6];
    const float* gat_ar0  = (const float*)d_in[7];
    const float* gat_b0   = (const float*)d_in[8];
    const float* gat_w1   = (const float*)d_in[9];
    const float* gat_al1  = (const float*)d_in[10];
    const float* gat_ar1  = (const float*)d_in[11];
    const float* gat_b1   = (const float*)d_in[12];
    const float* agg_q    = (const float*)d_in[13];
    const float* w_out1   = (const float*)d_in[14];
    const float* b_out1   = (const float*)d_in[15];
    const float* w_out2   = (const float*)d_in[16];
    const float* b_out2   = (const float*)d_in[17];
    const int*   esrc     = (const int*)d_in[18];
    const int*   edst     = (const int*)d_in[19];
    int E = in_sizes[18];

    cudaFuncSetAttribute(k_gemm, cudaFuncAttributeMaxDynamicSharedMemorySize,
                         GEMM_SMEM);

    const int lefts[5] = {0, 4, 7, 10, 13};

    k_prolog<<<33053, 256>>>(inputs, W_in, b_in, spat, temp,
                             gat_w0, gat_w1, edst, E);                    // 0
    k_csr1<<<1, 1024>>>(edst, E);                                         // 1
    k_csr2<<<4, 1024>>>(esrc);                                            // 2

    for (int it = 0; it < 5; it++) {
        k_gemm<<<(BB*NT)/128, 512, GEMM_SMEM>>>(0, it, lefts[it],
                                                gat_al0, gat_ar0);        // it0: idx 3 <- profiled
        k_agg0<<<2048, 256>>>(gat_b0);
        k_gemm<<<(BB*NT)/128, 512, GEMM_SMEM>>>(1, it, lefts[it],
                                                gat_al1, gat_ar1);
        k_agg1pool<<<2048, 256>>>(gat_b1, agg_q, it, lefts[it]);
    }

    k_out<<<BB*NN, 128>>>(w_out1, b_out1, w_out2, b_out2, (float*)d_out);
}